// round 16
// baseline (speedup 1.0000x reference)
#include <cuda_runtime.h>
#include <cuda_bf16.h>
#include <cstdint>

// Problem constants
#define T_    4
#define B_    32
#define C_    384
#define N_    256
#define TB_   128
#define HEADS 8
#define CH    48
#define BCN   3145728
#define TBCN  12582912

// ------------------------- device global scratch ---------------------------
__device__ float g_qlin[TBCN];
__device__ float g_klin[TBCN];
__device__ __nv_bfloat16 g_xs[3u * TBCN];       // x splits, [3][tb][c][n]
__device__ __nv_bfloat16 g_y[TBCN];             // y, [tb][c][n]
__device__ __nv_bfloat16 g_Aq[C_ * 3 * C_];     // [d][3*384] W-split concat
__device__ __nv_bfloat16 g_Ak[C_ * 3 * C_];
__device__ __nv_bfloat16 g_Ap[C_ * 3 * C_];
__device__ float g_bnqk[4 * C_];                // scq, shq, sck, shk
__device__ float g_bnp[2 * C_];                 // scp, shp

// ------------------------- PTX helpers (generic sm_80+) --------------------
__device__ __forceinline__ uint32_t smem_to_u32(const void* p) {
    uint32_t a;
    asm("{ .reg .u64 t; cvta.to.shared.u64 t, %1; cvt.u32.u64 %0, t; }"
        : "=r"(a) : "l"(p));
    return a;
}
__device__ __forceinline__ void cp_async16(uint32_t dst, const void* src) {
    asm volatile("cp.async.cg.shared.global [%0], [%1], 16;"
                 :: "r"(dst), "l"(src));
}
__device__ __forceinline__ void ldsm_x4(uint32_t& r0, uint32_t& r1,
                                        uint32_t& r2, uint32_t& r3,
                                        uint32_t addr) {
    asm volatile("ldmatrix.sync.aligned.m8n8.x4.shared.b16 {%0,%1,%2,%3}, [%4];"
                 : "=r"(r0), "=r"(r1), "=r"(r2), "=r"(r3) : "r"(addr));
}
__device__ __forceinline__ void ldsm_x4_t(uint32_t& r0, uint32_t& r1,
                                          uint32_t& r2, uint32_t& r3,
                                          uint32_t addr) {
    asm volatile("ldmatrix.sync.aligned.m8n8.x4.trans.shared.b16 {%0,%1,%2,%3}, [%4];"
                 : "=r"(r0), "=r"(r1), "=r"(r2), "=r"(r3) : "r"(addr));
}
__device__ __forceinline__ void mma16816(float* d,
                                         uint32_t a0, uint32_t a1,
                                         uint32_t a2, uint32_t a3,
                                         uint32_t b0, uint32_t b1) {
    asm volatile(
        "mma.sync.aligned.m16n8k16.row.col.f32.bf16.bf16.f32 "
        "{%0,%1,%2,%3}, {%4,%5,%6,%7}, {%8,%9}, {%0,%1,%2,%3};"
        : "+f"(d[0]), "+f"(d[1]), "+f"(d[2]), "+f"(d[3])
        : "r"(a0), "r"(a1), "r"(a2), "r"(a3), "r"(b0), "r"(b1));
}

// ---------------------------------------------------------------------------
// prep kernels
// ---------------------------------------------------------------------------
__global__ void bn_prep_all_kernel(const float* __restrict__ qg, const float* __restrict__ qb,
                                   const float* __restrict__ qm, const float* __restrict__ qv,
                                   const float* __restrict__ kg, const float* __restrict__ kb,
                                   const float* __restrict__ km, const float* __restrict__ kv,
                                   const float* __restrict__ pg, const float* __restrict__ pb,
                                   const float* __restrict__ pm, const float* __restrict__ pv,
                                   const float* __restrict__ pbias,
                                   float* __restrict__ bnqk, float* __restrict__ bnp)
{
    int d = threadIdx.x;
    if (d >= C_) return;
    if (blockIdx.x == 0) {
        float s = qg[d] * rsqrtf(qv[d] + 1e-5f);
        bnqk[d]      = s;
        bnqk[C_ + d] = qb[d] - qm[d] * s;
    } else if (blockIdx.x == 1) {
        float s = kg[d] * rsqrtf(kv[d] + 1e-5f);
        bnqk[2 * C_ + d] = s;
        bnqk[3 * C_ + d] = kb[d] - km[d] * s;
    } else {
        float s = pg[d] * rsqrtf(pv[d] + 1e-5f);
        bnp[d]      = s;
        bnp[C_ + d] = fmaf(s, pbias[d], pb[d] - pm[d] * s);
    }
}

__global__ void split_w_all_kernel(const float* __restrict__ Wq,
                                   const float* __restrict__ Wk,
                                   const float* __restrict__ Wp,
                                   __nv_bfloat16* __restrict__ Aq,
                                   __nv_bfloat16* __restrict__ Ak,
                                   __nv_bfloat16* __restrict__ Ap)
{
    int i = blockIdx.x * 256 + threadIdx.x;
    if (i >= C_ * C_) return;
    const float* W = (blockIdx.y == 0) ? Wq : (blockIdx.y == 1) ? Wk : Wp;
    __nv_bfloat16* A = (blockIdx.y == 0) ? Aq : (blockIdx.y == 1) ? Ak : Ap;
    int d = i / C_, c = i % C_;
    float w = W[i];
    __nv_bfloat16 b1 = __float2bfloat16(w);
    float r = w - __bfloat162float(b1);
    __nv_bfloat16 b2 = __float2bfloat16(r);
    float r2 = r - __bfloat162float(b2);
    __nv_bfloat16 b3 = __float2bfloat16(r2);
    size_t base = (size_t)d * (3 * C_) + c;
    A[base]          = b1;
    A[base + C_]     = b2;
    A[base + 2 * C_] = b3;
}

__global__ void split_x_kernel(const float* __restrict__ x,
                               __nv_bfloat16* __restrict__ xs)
{
    size_t i = ((size_t)blockIdx.x * 256 + threadIdx.x) * 4;
    float4 v = *(const float4*)(x + i);
    float vv[4] = {v.x, v.y, v.z, v.w};
    __nv_bfloat16 o1[4], o2[4], o3[4];
#pragma unroll
    for (int e = 0; e < 4; ++e) {
        __nv_bfloat16 b1 = __float2bfloat16(vv[e]);
        float r = vv[e] - __bfloat162float(b1);
        __nv_bfloat16 b2 = __float2bfloat16(r);
        float r2 = r - __bfloat162float(b2);
        o1[e] = b1; o2[e] = b2; o3[e] = __float2bfloat16(r2);
    }
    *(uint2*)(xs + i)                    = *(uint2*)o1;
    *(uint2*)(xs + (size_t)TBCN + i)     = *(uint2*)o2;
    *(uint2*)(xs + 2 * (size_t)TBCN + i) = *(uint2*)o3;
}

// ---------------------------------------------------------------------------
// DUAL-output HMMA GEMM for q+k — R12 loop body, FOUR pipeline stages.
// CTA tile 48(m) x 128(n), 192 threads, 6 warps (3m x 2n), BK=64.
// Stage: [Aq 6KB][Ak 6KB][B 16KB] = 28KB; 4 stages = 112KB; 2 CTAs/SM (224KB).
// ---------------------------------------------------------------------------
#define DSTAGE 28672
#define DSMEM  114688

__constant__ int c_IM[6] = {0, 0, 1, 0, 1, 2};
__constant__ int c_JM[6] = {0, 1, 0, 2, 1, 0};

__device__ __forceinline__ void dual_load_chunk(const __nv_bfloat16* __restrict__ Aq,
                                                const __nv_bfloat16* __restrict__ Ak,
                                                const __nv_bfloat16* __restrict__ Bx,
                                                int d0, int n0g, int tb, int kc,
                                                uint32_t stage, int tid)
{
    const int t = kc / 6, ks = kc % 6;
    const int i = c_IM[t], j = c_JM[t];
    const char* AgQ = (const char*)(Aq + (size_t)d0 * 1152 + i * 384 + ks * 64);
    const char* AgK = (const char*)(Ak + (size_t)d0 * 1152 + i * 384 + ks * 64);
    const char* Bg  = (const char*)(Bx + (size_t)j * TBCN +
                                    ((size_t)tb * C_ + ks * 64) * N_ + n0g);
#pragma unroll
    for (int q = 0; q < 2; ++q) {
        int idx = q * 192 + tid;
        int row = idx >> 3, seg = idx & 7;
        uint32_t off = (uint32_t)(row * 128) + (uint32_t)((seg ^ (row & 7)) << 4);
        cp_async16(stage + off,        AgQ + (size_t)row * 2304 + seg * 16);
        cp_async16(stage + 6144 + off, AgK + (size_t)row * 2304 + seg * 16);
    }
#pragma unroll
    for (int q = 0; q < 6; ++q) {
        int idx = q * 192 + tid;
        if (idx < 1024) {
            int row = idx >> 4, seg = idx & 15;
            uint32_t off = (uint32_t)(row * 256) + (uint32_t)((seg ^ (row & 7)) << 4);
            cp_async16(stage + 12288 + off, Bg + (size_t)row * 512 + seg * 16);
        }
    }
}

__global__ __launch_bounds__(192, 2)
void gemm_qk_dual_kernel(const __nv_bfloat16* __restrict__ Aq,
                         const __nv_bfloat16* __restrict__ Ak,
                         const __nv_bfloat16* __restrict__ Bx,
                         const float* __restrict__ bn,
                         float* __restrict__ outq,
                         float* __restrict__ outk)
{
    extern __shared__ char smem[];
    const uint32_t sbase = smem_to_u32(smem);
    const int tid  = threadIdx.x;
    const int wid  = tid >> 5;
    const int lane = tid & 31;
    const int nT = blockIdx.x, mT = blockIdx.y, tb = blockIdx.z;
    const int d0  = mT * 48;
    const int n0g = nT * 128;
    const int wm = wid % 3;
    const int wn = wid / 3;
    const int nch = 36;

    float accq[8][4], acck[8][4];
#pragma unroll
    for (int p = 0; p < 8; ++p)
#pragma unroll
        for (int q = 0; q < 4; ++q) { accq[p][q] = 0.f; acck[p][q] = 0.f; }

    dual_load_chunk(Aq, Ak, Bx, d0, n0g, tb, 0, sbase, tid);
    asm volatile("cp.async.commit_group;");
    dual_load_chunk(Aq, Ak, Bx, d0, n0g, tb, 1, sbase + DSTAGE, tid);
    asm volatile("cp.async.commit_group;");
    dual_load_chunk(Aq, Ak, Bx, d0, n0g, tb, 2, sbase + 2 * DSTAGE, tid);
    asm volatile("cp.async.commit_group;");

    for (int kc = 0; kc < nch; ++kc) {
        asm volatile("cp.async.wait_group 2;");   // chunk kc arrived
        __syncthreads();                          // compute(kc-1) fully drained

        if (kc + 3 < nch)
            dual_load_chunk(Aq, Ak, Bx, d0, n0g, tb, kc + 3,
                            sbase + (uint32_t)((kc + 3) & 3) * DSTAGE, tid);
        asm volatile("cp.async.commit_group;");

        const uint32_t aqb = sbase + (uint32_t)(kc & 3) * DSTAGE;
        const uint32_t akb = aqb + 6144;
        const uint32_t bbf = aqb + 12288;

#pragma unroll
        for (int kk = 0; kk < 4; ++kk) {
            uint32_t aq[4], ak[4];
            {
                int row = wm * 16 + (lane & 15);
                int seg = kk * 2 + (lane >> 4);
                uint32_t aoff = (uint32_t)(row * 128) + (uint32_t)((seg ^ (row & 7)) << 4);
                ldsm_x4(aq[0], aq[1], aq[2], aq[3], aqb + aoff);
                ldsm_x4(ak[0], ak[1], ak[2], ak[3], akb + aoff);
            }
            uint32_t b[4][4];
#pragma unroll
            for (int p = 0; p < 4; ++p) {
                int krow = kk * 16 + ((lane >> 3) & 1) * 8 + (lane & 7);
                int seg  = wn * 8 + p * 2 + (lane >> 4);
                uint32_t addr = bbf + (uint32_t)(krow * 256) +
                                (uint32_t)((seg ^ (krow & 7)) << 4);
                ldsm_x4_t(b[p][0], b[p][1], b[p][2], b[p][3], addr);
            }
#pragma unroll
            for (int p = 0; p < 4; ++p) {
                mma16816(accq[p * 2],     aq[0], aq[1], aq[2], aq[3], b[p][0], b[p][1]);
                mma16816(accq[p * 2 + 1], aq[0], aq[1], aq[2], aq[3], b[p][2], b[p][3]);
                mma16816(acck[p * 2],     ak[0], ak[1], ak[2], ak[3], b[p][0], b[p][1]);
                mma16816(acck[p * 2 + 1], ak[0], ak[1], ak[2], ak[3], b[p][2], b[p][3]);
            }
        }
    }

#pragma unroll
    for (int rr = 0; rr < 2; ++rr) {
        const int d = d0 + wm * 16 + (lane >> 2) + rr * 8;
        const float scq = bn[d],          shq = bn[C_ + d];
        const float sck = bn[2 * C_ + d], shk = bn[3 * C_ + d];
        float* opq = outq + ((size_t)tb * C_ + d) * N_ + n0g + wn * 64 + (lane & 3) * 2;
        float* opk = outk + ((size_t)tb * C_ + d) * N_ + n0g + wn * 64 + (lane & 3) * 2;
#pragma unroll
        for (int j = 0; j < 8; ++j) {
            float2 oq, ok;
            oq.x = fmaf(accq[j][rr * 2 + 0], scq, shq);
            oq.y = fmaf(accq[j][rr * 2 + 1], scq, shq);
            ok.x = fmaf(acck[j][rr * 2 + 0], sck, shk);
            ok.y = fmaf(acck[j][rr * 2 + 1], sck, shk);
            *(float2*)(opq + j * 8) = oq;
            *(float2*)(opk + j * 8) = ok;
        }
    }
}

// ---------------------------------------------------------------------------
// Proj GEMM v2 (R14, known good): B-tile reuse across 3 W-split terms.
// Chunk = ks (6 chunks); stage = [A0|A1|A2 18KB][B 16KB] = 34KB; 2 stages.
// ---------------------------------------------------------------------------
#define PSTAGE 34816
#define PSMEM  69632

__device__ __forceinline__ void proj_load_chunk(const __nv_bfloat16* __restrict__ A,
                                                const __nv_bfloat16* __restrict__ Bx,
                                                int d0, int n0g, int tb, int ks,
                                                uint32_t stage, int tid)
{
    const char* Bg = (const char*)(Bx + ((size_t)tb * C_ + ks * 64) * N_ + n0g);
#pragma unroll
    for (int t = 0; t < 3; ++t) {
        const char* Ag = (const char*)(A + (size_t)d0 * 1152 + t * 384 + ks * 64);
#pragma unroll
        for (int q = 0; q < 2; ++q) {
            int idx = q * 192 + tid;
            int row = idx >> 3, seg = idx & 7;
            uint32_t off = (uint32_t)(row * 128) + (uint32_t)((seg ^ (row & 7)) << 4);
            cp_async16(stage + t * 6144 + off, Ag + (size_t)row * 2304 + seg * 16);
        }
    }
#pragma unroll
    for (int q = 0; q < 6; ++q) {
        int idx = q * 192 + tid;
        if (idx < 1024) {
            int row = idx >> 4, seg = idx & 15;
            uint32_t off = (uint32_t)(row * 256) + (uint32_t)((seg ^ (row & 7)) << 4);
            cp_async16(stage + 18432 + off, Bg + (size_t)row * 512 + seg * 16);
        }
    }
}

__global__ __launch_bounds__(192, 3)
void gemm_proj_kernel(const __nv_bfloat16* __restrict__ A,
                      const __nv_bfloat16* __restrict__ Bx,
                      const float* __restrict__ bn,
                      float* __restrict__ out)
{
    extern __shared__ char smem[];
    const uint32_t sbase = smem_to_u32(smem);
    const int tid  = threadIdx.x;
    const int wid  = tid >> 5;
    const int lane = tid & 31;
    const int nT = blockIdx.x, mT = blockIdx.y, tb = blockIdx.z;
    const int d0  = mT * 48;
    const int n0g = nT * 128;
    const int wm = wid % 3;
    const int wn = wid / 3;
    const int nch = 6;

    float acc[8][4];
#pragma unroll
    for (int p = 0; p < 8; ++p)
#pragma unroll
        for (int q = 0; q < 4; ++q) acc[p][q] = 0.f;

    proj_load_chunk(A, Bx, d0, n0g, tb, 0, sbase, tid);
    asm volatile("cp.async.commit_group;");

    for (int kc = 0; kc < nch; ++kc) {
        asm volatile("cp.async.wait_group 0;");
        __syncthreads();

        if (kc + 1 < nch) {
            proj_load_chunk(A, Bx, d0, n0g, tb, kc + 1,
                            sbase + (uint32_t)((kc + 1) & 1) * PSTAGE, tid);
            asm volatile("cp.async.commit_group;");
        }

        const uint32_t ab  = sbase + (uint32_t)(kc & 1) * PSTAGE;
        const uint32_t bbf = ab + 18432;

#pragma unroll
        for (int kk = 0; kk < 4; ++kk) {
            uint32_t b[4][4];
#pragma unroll
            for (int p = 0; p < 4; ++p) {
                int krow = kk * 16 + ((lane >> 3) & 1) * 8 + (lane & 7);
                int seg  = wn * 8 + p * 2 + (lane >> 4);
                uint32_t addr = bbf + (uint32_t)(krow * 256) +
                                (uint32_t)((seg ^ (krow & 7)) << 4);
                ldsm_x4_t(b[p][0], b[p][1], b[p][2], b[p][3], addr);
            }
#pragma unroll
            for (int t = 0; t < 3; ++t) {
                uint32_t a[4];
                int row = wm * 16 + (lane & 15);
                int seg = kk * 2 + (lane >> 4);
                uint32_t aoff = (uint32_t)(row * 128) + (uint32_t)((seg ^ (row & 7)) << 4);
                ldsm_x4(a[0], a[1], a[2], a[3], ab + t * 6144 + aoff);
#pragma unroll
                for (int p = 0; p < 4; ++p) {
                    mma16816(acc[p * 2],     a[0], a[1], a[2], a[3], b[p][0], b[p][1]);
                    mma16816(acc[p * 2 + 1], a[0], a[1], a[2], a[3], b[p][2], b[p][3]);
                }
            }
        }
    }

#pragma unroll
    for (int rr = 0; rr < 2; ++rr) {
        const int d = d0 + wm * 16 + (lane >> 2) + rr * 8;
        const float sc = bn[d];
        const float sh = bn[C_ + d];
        float* op = out + ((size_t)tb * C_ + d) * N_ + n0g + wn * 64 + (lane & 3) * 2;
#pragma unroll
        for (int j = 0; j < 8; ++j) {
            float2 o;
            o.x = fmaf(acc[j][rr * 2 + 0], sc, sh);
            o.y = fmaf(acc[j][rr * 2 + 1], sc, sh);
            *(float2*)(op + j * 8) = o;
        }
    }
}

// ---------------------------------------------------------------------------
// Fused: q-LIF -> head-sum -> attn-LIF -> k-LIF -> y (bf16)
// ---------------------------------------------------------------------------
__global__ void attn_fuse_kernel(const float* __restrict__ qlin,
                                 const float* __restrict__ klin,
                                 __nv_bfloat16* __restrict__ y)
{
    const int bh = blockIdx.x;
    const int b  = bh >> 3;
    const int hd = bh & 7;
    const int n  = threadIdx.x;
    const size_t tstr = (size_t)BCN;

    float qs[4] = {0.f, 0.f, 0.f, 0.f};
    const size_t base = ((size_t)b * C_ + hd * CH) * N_ + n;

    for (int c = 0; c < CH; ++c) {
        const size_t idx = base + (size_t)c * N_;
        float v = 0.f;
#pragma unroll
        for (int t = 0; t < T_; ++t) {
            const float xq = qlin[idx + (size_t)t * tstr];
            const float h  = v + (xq - v) * 0.5f;
            const bool  sp = (h >= 1.0f);
            qs[t] += sp ? 1.f : 0.f;
            v = sp ? 0.f : h;
        }
    }

    float a[4];
    {
        float v = 0.f;
#pragma unroll
        for (int t = 0; t < T_; ++t) {
            const float h = v + (qs[t] - v) * 0.5f;
            const bool sp = (h >= 0.5f);
            a[t] = sp ? 1.f : 0.f;
            v = sp ? 0.f : h;
        }
    }

    for (int c = 0; c < CH; ++c) {
        const size_t idx = base + (size_t)c * N_;
        float v = 0.f;
#pragma unroll
        for (int t = 0; t < T_; ++t) {
            const float xk = klin[idx + (size_t)t * tstr];
            const float h  = v + (xk - v) * 0.5f;
            const bool  sp = (h >= 1.0f);
            const float yv = (sp ? 1.f : 0.f) * a[t];
            y[idx + (size_t)t * tstr] = __float2bfloat16(yv);
            v = sp ? 0.f : h;
        }
    }
}

// ---------------------------------------------------------------------------
// Final LIF -> spikes to d_out (float4 vectorized)
// ---------------------------------------------------------------------------
__global__ void final_lif_kernel(const float4* __restrict__ p,
                                 float4* __restrict__ o)
{
    const size_t i = (size_t)blockIdx.x * blockDim.x + threadIdx.x;
    float4 v = {0.f, 0.f, 0.f, 0.f};
#pragma unroll
    for (int t = 0; t < T_; ++t) {
        const float4 x = p[i + (size_t)t * (BCN / 4)];
        float4 s;
        float h;
        h = v.x + (x.x - v.x) * 0.5f; s.x = (h >= 1.0f) ? 1.f : 0.f; v.x = (h >= 1.0f) ? 0.f : h;
        h = v.y + (x.y - v.y) * 0.5f; s.y = (h >= 1.0f) ? 1.f : 0.f; v.y = (h >= 1.0f) ? 0.f : h;
        h = v.z + (x.z - v.z) * 0.5f; s.z = (h >= 1.0f) ? 1.f : 0.f; v.z = (h >= 1.0f) ? 0.f : h;
        h = v.w + (x.w - v.w) * 0.5f; s.w = (h >= 1.0f) ? 1.f : 0.f; v.w = (h >= 1.0f) ? 0.f : h;
        o[i + (size_t)t * (BCN / 4)] = s;
    }
}

// ---------------------------------------------------------------------------
extern "C" void kernel_launch(void* const* d_in, const int* in_sizes, int n_in,
                              void* d_out, int out_size)
{
    const float* x        = (const float*)d_in[0];
    const float* q_w      = (const float*)d_in[1];
    const float* q_gamma  = (const float*)d_in[2];
    const float* q_beta   = (const float*)d_in[3];
    const float* q_mean   = (const float*)d_in[4];
    const float* q_var    = (const float*)d_in[5];
    const float* k_w      = (const float*)d_in[6];
    const float* k_gamma  = (const float*)d_in[7];
    const float* k_beta   = (const float*)d_in[8];
    const float* k_mean   = (const float*)d_in[9];
    const float* k_var    = (const float*)d_in[10];
    const float* p_w      = (const float*)d_in[11];
    const float* p_gamma  = (const float*)d_in[12];
    const float* p_beta   = (const float*)d_in[13];
    const float* p_mean   = (const float*)d_in[14];
    const float* p_var    = (const float*)d_in[15];
    const float* p_b      = (const float*)d_in[16];

    float *qlin, *klin, *bnqk, *bnp;
    __nv_bfloat16 *xs, *y, *Aq, *Ak, *Ap;
    cudaGetSymbolAddress((void**)&qlin, g_qlin);
    cudaGetSymbolAddress((void**)&klin, g_klin);
    cudaGetSymbolAddress((void**)&xs, g_xs);
    cudaGetSymbolAddress((void**)&y, g_y);
    cudaGetSymbolAddress((void**)&Aq, g_Aq);
    cudaGetSymbolAddress((void**)&Ak, g_Ak);
    cudaGetSymbolAddress((void**)&Ap, g_Ap);
    cudaGetSymbolAddress((void**)&bnqk, g_bnqk);
    cudaGetSymbolAddress((void**)&bnp, g_bnp);

    cudaFuncSetAttribute(gemm_qk_dual_kernel,
                         cudaFuncAttributeMaxDynamicSharedMemorySize, DSMEM);
    cudaFuncSetAttribute(gemm_proj_kernel,
                         cudaFuncAttributeMaxDynamicSharedMemorySize, PSMEM);

    // prep
    bn_prep_all_kernel<<<3, C_>>>(q_gamma, q_beta, q_mean, q_var,
                                  k_gamma, k_beta, k_mean, k_var,
                                  p_gamma, p_beta, p_mean, p_var, p_b,
                                  bnqk, bnp);
    split_w_all_kernel<<<dim3((C_ * C_ + 255) / 256, 3), 256>>>(q_w, k_w, p_w,
                                                                Aq, Ak, Ap);
    split_x_kernel<<<TBCN / 1024, 256>>>(x, xs);

    // dual q+k GEMM (R12 body, 4-stage pipeline), occ 2
    gemm_qk_dual_kernel<<<dim3(2, 8, 128), 192, DSMEM>>>(Aq, Ak, xs, bnqk,
                                                         qlin, klin);

    attn_fuse_kernel<<<B_ * HEADS, N_>>>(qlin, klin, y);

    // proj GEMM v2 (B reuse across 3 W terms), occ 3
    gemm_proj_kernel<<<dim3(2, 8, 128), 192, PSMEM>>>(Ap, y, bnp, qlin);

    final_lif_kernel<<<BCN / 1024, 256>>>((const float4*)qlin, (float4*)d_out);
}

// round 17
// speedup vs baseline: 1.0632x; 1.0632x over previous
#include <cuda_runtime.h>
#include <cuda_bf16.h>
#include <cstdint>

// Problem constants
#define T_    4
#define B_    32
#define C_    384
#define N_    256
#define TB_   128
#define HEADS 8
#define CH    48
#define BCN   3145728
#define TBCN  12582912

// ------------------------- device global scratch ---------------------------
__device__ float g_qlin[TBCN];
__device__ float g_klin[TBCN];
__device__ __nv_bfloat16 g_xs[3u * TBCN];       // x splits, [3][tb][c][n]
__device__ __nv_bfloat16 g_y[TBCN];             // y, [tb][c][n]
__device__ __nv_bfloat16 g_Aq[C_ * 3 * C_];     // [d][3*384] W-split concat
__device__ __nv_bfloat16 g_Ak[C_ * 3 * C_];
__device__ __nv_bfloat16 g_Ap[C_ * 3 * C_];
__device__ float g_bnqk[4 * C_];                // scq, shq, sck, shk
__device__ float g_bnp[2 * C_];                 // scp, shp

// ------------------------- PTX helpers (generic sm_80+) --------------------
__device__ __forceinline__ uint32_t smem_to_u32(const void* p) {
    uint32_t a;
    asm("{ .reg .u64 t; cvta.to.shared.u64 t, %1; cvt.u32.u64 %0, t; }"
        : "=r"(a) : "l"(p));
    return a;
}
__device__ __forceinline__ void cp_async16(uint32_t dst, const void* src) {
    asm volatile("cp.async.cg.shared.global [%0], [%1], 16;"
                 :: "r"(dst), "l"(src));
}
__device__ __forceinline__ void ldsm_x4(uint32_t& r0, uint32_t& r1,
                                        uint32_t& r2, uint32_t& r3,
                                        uint32_t addr) {
    asm volatile("ldmatrix.sync.aligned.m8n8.x4.shared.b16 {%0,%1,%2,%3}, [%4];"
                 : "=r"(r0), "=r"(r1), "=r"(r2), "=r"(r3) : "r"(addr));
}
__device__ __forceinline__ void ldsm_x4_t(uint32_t& r0, uint32_t& r1,
                                          uint32_t& r2, uint32_t& r3,
                                          uint32_t addr) {
    asm volatile("ldmatrix.sync.aligned.m8n8.x4.trans.shared.b16 {%0,%1,%2,%3}, [%4];"
                 : "=r"(r0), "=r"(r1), "=r"(r2), "=r"(r3) : "r"(addr));
}
__device__ __forceinline__ void mma16816(float* d,
                                         uint32_t a0, uint32_t a1,
                                         uint32_t a2, uint32_t a3,
                                         uint32_t b0, uint32_t b1) {
    asm volatile(
        "mma.sync.aligned.m16n8k16.row.col.f32.bf16.bf16.f32 "
        "{%0,%1,%2,%3}, {%4,%5,%6,%7}, {%8,%9}, {%0,%1,%2,%3};"
        : "+f"(d[0]), "+f"(d[1]), "+f"(d[2]), "+f"(d[3])
        : "r"(a0), "r"(a1), "r"(a2), "r"(a3), "r"(b0), "r"(b1));
}

// ---------------------------------------------------------------------------
// prep kernels
// ---------------------------------------------------------------------------
__global__ void bn_prep_all_kernel(const float* __restrict__ qg, const float* __restrict__ qb,
                                   const float* __restrict__ qm, const float* __restrict__ qv,
                                   const float* __restrict__ kg, const float* __restrict__ kb,
                                   const float* __restrict__ km, const float* __restrict__ kv,
                                   const float* __restrict__ pg, const float* __restrict__ pb,
                                   const float* __restrict__ pm, const float* __restrict__ pv,
                                   const float* __restrict__ pbias,
                                   float* __restrict__ bnqk, float* __restrict__ bnp)
{
    int d = threadIdx.x;
    if (d >= C_) return;
    if (blockIdx.x == 0) {
        float s = qg[d] * rsqrtf(qv[d] + 1e-5f);
        bnqk[d]      = s;
        bnqk[C_ + d] = qb[d] - qm[d] * s;
    } else if (blockIdx.x == 1) {
        float s = kg[d] * rsqrtf(kv[d] + 1e-5f);
        bnqk[2 * C_ + d] = s;
        bnqk[3 * C_ + d] = kb[d] - km[d] * s;
    } else {
        float s = pg[d] * rsqrtf(pv[d] + 1e-5f);
        bnp[d]      = s;
        bnp[C_ + d] = fmaf(s, pbias[d], pb[d] - pm[d] * s);
    }
}

__global__ void split_w_all_kernel(const float* __restrict__ Wq,
                                   const float* __restrict__ Wk,
                                   const float* __restrict__ Wp,
                                   __nv_bfloat16* __restrict__ Aq,
                                   __nv_bfloat16* __restrict__ Ak,
                                   __nv_bfloat16* __restrict__ Ap)
{
    int i = blockIdx.x * 256 + threadIdx.x;
    if (i >= C_ * C_) return;
    const float* W = (blockIdx.y == 0) ? Wq : (blockIdx.y == 1) ? Wk : Wp;
    __nv_bfloat16* A = (blockIdx.y == 0) ? Aq : (blockIdx.y == 1) ? Ak : Ap;
    int d = i / C_, c = i % C_;
    float w = W[i];
    __nv_bfloat16 b1 = __float2bfloat16(w);
    float r = w - __bfloat162float(b1);
    __nv_bfloat16 b2 = __float2bfloat16(r);
    float r2 = r - __bfloat162float(b2);
    __nv_bfloat16 b3 = __float2bfloat16(r2);
    size_t base = (size_t)d * (3 * C_) + c;
    A[base]          = b1;
    A[base + C_]     = b2;
    A[base + 2 * C_] = b3;
}

__global__ void split_x_kernel(const float* __restrict__ x,
                               __nv_bfloat16* __restrict__ xs)
{
    size_t i = ((size_t)blockIdx.x * 256 + threadIdx.x) * 4;
    float4 v = *(const float4*)(x + i);
    float vv[4] = {v.x, v.y, v.z, v.w};
    __nv_bfloat16 o1[4], o2[4], o3[4];
#pragma unroll
    for (int e = 0; e < 4; ++e) {
        __nv_bfloat16 b1 = __float2bfloat16(vv[e]);
        float r = vv[e] - __bfloat162float(b1);
        __nv_bfloat16 b2 = __float2bfloat16(r);
        float r2 = r - __bfloat162float(b2);
        o1[e] = b1; o2[e] = b2; o3[e] = __float2bfloat16(r2);
    }
    *(uint2*)(xs + i)                    = *(uint2*)o1;
    *(uint2*)(xs + (size_t)TBCN + i)     = *(uint2*)o2;
    *(uint2*)(xs + 2 * (size_t)TBCN + i) = *(uint2*)o3;
}

// ---------------------------------------------------------------------------
// DUAL-output HMMA GEMM for q+k — R12 version (best known: 265us).
// CTA tile 48(m) x 128(n), 192 threads, 6 warps (3m x 2n), BK=64, 3 stages.
// Stage: [Aq 6KB][Ak 6KB][B 16KB] = 28KB; 3 stages = 84KB; 2 CTAs/SM.
// ---------------------------------------------------------------------------
#define DSTAGE 28672
#define DSMEM  86016

__constant__ int c_IM[6] = {0, 0, 1, 0, 1, 2};
__constant__ int c_JM[6] = {0, 1, 0, 2, 1, 0};

__device__ __forceinline__ void dual_load_chunk(const __nv_bfloat16* __restrict__ Aq,
                                                const __nv_bfloat16* __restrict__ Ak,
                                                const __nv_bfloat16* __restrict__ Bx,
                                                int d0, int n0g, int tb, int kc,
                                                uint32_t stage, int tid)
{
    const int t = kc / 6, ks = kc % 6;
    const int i = c_IM[t], j = c_JM[t];
    const char* AgQ = (const char*)(Aq + (size_t)d0 * 1152 + i * 384 + ks * 64);
    const char* AgK = (const char*)(Ak + (size_t)d0 * 1152 + i * 384 + ks * 64);
    const char* Bg  = (const char*)(Bx + (size_t)j * TBCN +
                                    ((size_t)tb * C_ + ks * 64) * N_ + n0g);
#pragma unroll
    for (int q = 0; q < 2; ++q) {
        int idx = q * 192 + tid;
        int row = idx >> 3, seg = idx & 7;
        uint32_t off = (uint32_t)(row * 128) + (uint32_t)((seg ^ (row & 7)) << 4);
        cp_async16(stage + off,        AgQ + (size_t)row * 2304 + seg * 16);
        cp_async16(stage + 6144 + off, AgK + (size_t)row * 2304 + seg * 16);
    }
#pragma unroll
    for (int q = 0; q < 6; ++q) {
        int idx = q * 192 + tid;
        if (idx < 1024) {
            int row = idx >> 4, seg = idx & 15;
            uint32_t off = (uint32_t)(row * 256) + (uint32_t)((seg ^ (row & 7)) << 4);
            cp_async16(stage + 12288 + off, Bg + (size_t)row * 512 + seg * 16);
        }
    }
}

__global__ __launch_bounds__(192, 2)
void gemm_qk_dual_kernel(const __nv_bfloat16* __restrict__ Aq,
                         const __nv_bfloat16* __restrict__ Ak,
                         const __nv_bfloat16* __restrict__ Bx,
                         const float* __restrict__ bn,
                         float* __restrict__ outq,
                         float* __restrict__ outk)
{
    extern __shared__ char smem[];
    const uint32_t sbase = smem_to_u32(smem);
    const int tid  = threadIdx.x;
    const int wid  = tid >> 5;
    const int lane = tid & 31;
    const int nT = blockIdx.x, mT = blockIdx.y, tb = blockIdx.z;
    const int d0  = mT * 48;
    const int n0g = nT * 128;
    const int wm = wid % 3;
    const int wn = wid / 3;
    const int nch = 36;

    float accq[8][4], acck[8][4];
#pragma unroll
    for (int p = 0; p < 8; ++p)
#pragma unroll
        for (int q = 0; q < 4; ++q) { accq[p][q] = 0.f; acck[p][q] = 0.f; }

    dual_load_chunk(Aq, Ak, Bx, d0, n0g, tb, 0, sbase, tid);
    asm volatile("cp.async.commit_group;");
    dual_load_chunk(Aq, Ak, Bx, d0, n0g, tb, 1, sbase + DSTAGE, tid);
    asm volatile("cp.async.commit_group;");

    for (int kc = 0; kc < nch; ++kc) {
        asm volatile("cp.async.wait_group 1;");
        __syncthreads();

        if (kc + 2 < nch)
            dual_load_chunk(Aq, Ak, Bx, d0, n0g, tb, kc + 2,
                            sbase + (uint32_t)((kc + 2) % 3) * DSTAGE, tid);
        asm volatile("cp.async.commit_group;");

        const uint32_t aqb = sbase + (uint32_t)(kc % 3) * DSTAGE;
        const uint32_t akb = aqb + 6144;
        const uint32_t bbf = aqb + 12288;

#pragma unroll
        for (int kk = 0; kk < 4; ++kk) {
            uint32_t aq[4], ak[4];
            {
                int row = wm * 16 + (lane & 15);
                int seg = kk * 2 + (lane >> 4);
                uint32_t aoff = (uint32_t)(row * 128) + (uint32_t)((seg ^ (row & 7)) << 4);
                ldsm_x4(aq[0], aq[1], aq[2], aq[3], aqb + aoff);
                ldsm_x4(ak[0], ak[1], ak[2], ak[3], akb + aoff);
            }
            uint32_t b[4][4];
#pragma unroll
            for (int p = 0; p < 4; ++p) {
                int krow = kk * 16 + ((lane >> 3) & 1) * 8 + (lane & 7);
                int seg  = wn * 8 + p * 2 + (lane >> 4);
                uint32_t addr = bbf + (uint32_t)(krow * 256) +
                                (uint32_t)((seg ^ (krow & 7)) << 4);
                ldsm_x4_t(b[p][0], b[p][1], b[p][2], b[p][3], addr);
            }
#pragma unroll
            for (int p = 0; p < 4; ++p) {
                mma16816(accq[p * 2],     aq[0], aq[1], aq[2], aq[3], b[p][0], b[p][1]);
                mma16816(accq[p * 2 + 1], aq[0], aq[1], aq[2], aq[3], b[p][2], b[p][3]);
                mma16816(acck[p * 2],     ak[0], ak[1], ak[2], ak[3], b[p][0], b[p][1]);
                mma16816(acck[p * 2 + 1], ak[0], ak[1], ak[2], ak[3], b[p][2], b[p][3]);
            }
        }
    }

#pragma unroll
    for (int rr = 0; rr < 2; ++rr) {
        const int d = d0 + wm * 16 + (lane >> 2) + rr * 8;
        const float scq = bn[d],          shq = bn[C_ + d];
        const float sck = bn[2 * C_ + d], shk = bn[3 * C_ + d];
        float* opq = outq + ((size_t)tb * C_ + d) * N_ + n0g + wn * 64 + (lane & 3) * 2;
        float* opk = outk + ((size_t)tb * C_ + d) * N_ + n0g + wn * 64 + (lane & 3) * 2;
#pragma unroll
        for (int j = 0; j < 8; ++j) {
            float2 oq, ok;
            oq.x = fmaf(accq[j][rr * 2 + 0], scq, shq);
            oq.y = fmaf(accq[j][rr * 2 + 1], scq, shq);
            ok.x = fmaf(acck[j][rr * 2 + 0], sck, shk);
            ok.y = fmaf(acck[j][rr * 2 + 1], sck, shk);
            *(float2*)(opq + j * 8) = oq;
            *(float2*)(opk + j * 8) = ok;
        }
    }
}

// ---------------------------------------------------------------------------
// Proj GEMM v2 (R14, known good): B-tile reuse across 3 W-split terms.
// ---------------------------------------------------------------------------
#define PSTAGE 34816
#define PSMEM  69632

__device__ __forceinline__ void proj_load_chunk(const __nv_bfloat16* __restrict__ A,
                                                const __nv_bfloat16* __restrict__ Bx,
                                                int d0, int n0g, int tb, int ks,
                                                uint32_t stage, int tid)
{
    const char* Bg = (const char*)(Bx + ((size_t)tb * C_ + ks * 64) * N_ + n0g);
#pragma unroll
    for (int t = 0; t < 3; ++t) {
        const char* Ag = (const char*)(A + (size_t)d0 * 1152 + t * 384 + ks * 64);
#pragma unroll
        for (int q = 0; q < 2; ++q) {
            int idx = q * 192 + tid;
            int row = idx >> 3, seg = idx & 7;
            uint32_t off = (uint32_t)(row * 128) + (uint32_t)((seg ^ (row & 7)) << 4);
            cp_async16(stage + t * 6144 + off, Ag + (size_t)row * 2304 + seg * 16);
        }
    }
#pragma unroll
    for (int q = 0; q < 6; ++q) {
        int idx = q * 192 + tid;
        if (idx < 1024) {
            int row = idx >> 4, seg = idx & 15;
            uint32_t off = (uint32_t)(row * 256) + (uint32_t)((seg ^ (row & 7)) << 4);
            cp_async16(stage + 18432 + off, Bg + (size_t)row * 512 + seg * 16);
        }
    }
}

__global__ __launch_bounds__(192, 3)
void gemm_proj_kernel(const __nv_bfloat16* __restrict__ A,
                      const __nv_bfloat16* __restrict__ Bx,
                      const float* __restrict__ bn,
                      float* __restrict__ out)
{
    extern __shared__ char smem[];
    const uint32_t sbase = smem_to_u32(smem);
    const int tid  = threadIdx.x;
    const int wid  = tid >> 5;
    const int lane = tid & 31;
    const int nT = blockIdx.x, mT = blockIdx.y, tb = blockIdx.z;
    const int d0  = mT * 48;
    const int n0g = nT * 128;
    const int wm = wid % 3;
    const int wn = wid / 3;
    const int nch = 6;

    float acc[8][4];
#pragma unroll
    for (int p = 0; p < 8; ++p)
#pragma unroll
        for (int q = 0; q < 4; ++q) acc[p][q] = 0.f;

    proj_load_chunk(A, Bx, d0, n0g, tb, 0, sbase, tid);
    asm volatile("cp.async.commit_group;");

    for (int kc = 0; kc < nch; ++kc) {
        asm volatile("cp.async.wait_group 0;");
        __syncthreads();

        if (kc + 1 < nch) {
            proj_load_chunk(A, Bx, d0, n0g, tb, kc + 1,
                            sbase + (uint32_t)((kc + 1) & 1) * PSTAGE, tid);
            asm volatile("cp.async.commit_group;");
        }

        const uint32_t ab  = sbase + (uint32_t)(kc & 1) * PSTAGE;
        const uint32_t bbf = ab + 18432;

#pragma unroll
        for (int kk = 0; kk < 4; ++kk) {
            uint32_t b[4][4];
#pragma unroll
            for (int p = 0; p < 4; ++p) {
                int krow = kk * 16 + ((lane >> 3) & 1) * 8 + (lane & 7);
                int seg  = wn * 8 + p * 2 + (lane >> 4);
                uint32_t addr = bbf + (uint32_t)(krow * 256) +
                                (uint32_t)((seg ^ (krow & 7)) << 4);
                ldsm_x4_t(b[p][0], b[p][1], b[p][2], b[p][3], addr);
            }
#pragma unroll
            for (int t = 0; t < 3; ++t) {
                uint32_t a[4];
                int row = wm * 16 + (lane & 15);
                int seg = kk * 2 + (lane >> 4);
                uint32_t aoff = (uint32_t)(row * 128) + (uint32_t)((seg ^ (row & 7)) << 4);
                ldsm_x4(a[0], a[1], a[2], a[3], ab + t * 6144 + aoff);
#pragma unroll
                for (int p = 0; p < 4; ++p) {
                    mma16816(acc[p * 2],     a[0], a[1], a[2], a[3], b[p][0], b[p][1]);
                    mma16816(acc[p * 2 + 1], a[0], a[1], a[2], a[3], b[p][2], b[p][3]);
                }
            }
        }
    }

#pragma unroll
    for (int rr = 0; rr < 2; ++rr) {
        const int d = d0 + wm * 16 + (lane >> 2) + rr * 8;
        const float sc = bn[d];
        const float sh = bn[C_ + d];
        float* op = out + ((size_t)tb * C_ + d) * N_ + n0g + wn * 64 + (lane & 3) * 2;
#pragma unroll
        for (int j = 0; j < 8; ++j) {
            float2 o;
            o.x = fmaf(acc[j][rr * 2 + 0], sc, sh);
            o.y = fmaf(acc[j][rr * 2 + 1], sc, sh);
            *(float2*)(op + j * 8) = o;
        }
    }
}

// ---------------------------------------------------------------------------
// Fused attn, 4-way channel split: block = (b, head), 1024 threads.
// Quarter qd handles channels [qd*12, qd*12+12). q-spike partial counts are
// exact small integers -> smem combine is exact regardless of order.
// ---------------------------------------------------------------------------
__global__ __launch_bounds__(1024)
void attn_fuse_kernel(const float* __restrict__ qlin,
                      const float* __restrict__ klin,
                      __nv_bfloat16* __restrict__ y)
{
    __shared__ float s_part[4][4][256];   // [quarter][t][n]
    __shared__ float s_att[4][256];       // [t][n]

    const int bh = blockIdx.x;
    const int b  = bh >> 3;
    const int hd = bh & 7;
    const int tid = threadIdx.x;
    const int qd = tid >> 8;              // 0..3
    const int n  = tid & 255;
    const size_t tstr = (size_t)BCN;
    const size_t base = ((size_t)b * C_ + hd * CH) * N_ + n;
    const int c0 = qd * 12;

    float qs[4] = {0.f, 0.f, 0.f, 0.f};
#pragma unroll 4
    for (int c = c0; c < c0 + 12; ++c) {
        const size_t idx = base + (size_t)c * N_;
        float v = 0.f;
#pragma unroll
        for (int t = 0; t < T_; ++t) {
            const float xq = qlin[idx + (size_t)t * tstr];
            const float h  = v + (xq - v) * 0.5f;
            const bool  sp = (h >= 1.0f);
            qs[t] += sp ? 1.f : 0.f;
            v = sp ? 0.f : h;
        }
    }
#pragma unroll
    for (int t = 0; t < T_; ++t) s_part[qd][t][n] = qs[t];
    __syncthreads();

    if (qd == 0) {
        float v = 0.f;
#pragma unroll
        for (int t = 0; t < T_; ++t) {
            const float q = s_part[0][t][n] + s_part[1][t][n] +
                            s_part[2][t][n] + s_part[3][t][n];
            const float h = v + (q - v) * 0.5f;
            const bool sp = (h >= 0.5f);
            s_att[t][n] = sp ? 1.f : 0.f;
            v = sp ? 0.f : h;
        }
    }
    __syncthreads();

    float a[4];
#pragma unroll
    for (int t = 0; t < T_; ++t) a[t] = s_att[t][n];

#pragma unroll 4
    for (int c = c0; c < c0 + 12; ++c) {
        const size_t idx = base + (size_t)c * N_;
        float v = 0.f;
#pragma unroll
        for (int t = 0; t < T_; ++t) {
            const float xk = klin[idx + (size_t)t * tstr];
            const float h  = v + (xk - v) * 0.5f;
            const bool  sp = (h >= 1.0f);
            y[idx + (size_t)t * tstr] = __float2bfloat16((sp ? 1.f : 0.f) * a[t]);
            v = sp ? 0.f : h;
        }
    }
}

// ---------------------------------------------------------------------------
// Final LIF -> spikes to d_out (float4 vectorized)
// ---------------------------------------------------------------------------
__global__ void final_lif_kernel(const float4* __restrict__ p,
                                 float4* __restrict__ o)
{
    const size_t i = (size_t)blockIdx.x * blockDim.x + threadIdx.x;
    float4 v = {0.f, 0.f, 0.f, 0.f};
#pragma unroll
    for (int t = 0; t < T_; ++t) {
        const float4 x = p[i + (size_t)t * (BCN / 4)];
        float4 s;
        float h;
        h = v.x + (x.x - v.x) * 0.5f; s.x = (h >= 1.0f) ? 1.f : 0.f; v.x = (h >= 1.0f) ? 0.f : h;
        h = v.y + (x.y - v.y) * 0.5f; s.y = (h >= 1.0f) ? 1.f : 0.f; v.y = (h >= 1.0f) ? 0.f : h;
        h = v.z + (x.z - v.z) * 0.5f; s.z = (h >= 1.0f) ? 1.f : 0.f; v.z = (h >= 1.0f) ? 0.f : h;
        h = v.w + (x.w - v.w) * 0.5f; s.w = (h >= 1.0f) ? 1.f : 0.f; v.w = (h >= 1.0f) ? 0.f : h;
        o[i + (size_t)t * (BCN / 4)] = s;
    }
}

// ---------------------------------------------------------------------------
extern "C" void kernel_launch(void* const* d_in, const int* in_sizes, int n_in,
                              void* d_out, int out_size)
{
    const float* x        = (const float*)d_in[0];
    const float* q_w      = (const float*)d_in[1];
    const float* q_gamma  = (const float*)d_in[2];
    const float* q_beta   = (const float*)d_in[3];
    const float* q_mean   = (const float*)d_in[4];
    const float* q_var    = (const float*)d_in[5];
    const float* k_w      = (const float*)d_in[6];
    const float* k_gamma  = (const float*)d_in[7];
    const float* k_beta   = (const float*)d_in[8];
    const float* k_mean   = (const float*)d_in[9];
    const float* k_var    = (const float*)d_in[10];
    const float* p_w      = (const float*)d_in[11];
    const float* p_gamma  = (const float*)d_in[12];
    const float* p_beta   = (const float*)d_in[13];
    const float* p_mean   = (const float*)d_in[14];
    const float* p_var    = (const float*)d_in[15];
    const float* p_b      = (const float*)d_in[16];

    float *qlin, *klin, *bnqk, *bnp;
    __nv_bfloat16 *xs, *y, *Aq, *Ak, *Ap;
    cudaGetSymbolAddress((void**)&qlin, g_qlin);
    cudaGetSymbolAddress((void**)&klin, g_klin);
    cudaGetSymbolAddress((void**)&xs, g_xs);
    cudaGetSymbolAddress((void**)&y, g_y);
    cudaGetSymbolAddress((void**)&Aq, g_Aq);
    cudaGetSymbolAddress((void**)&Ak, g_Ak);
    cudaGetSymbolAddress((void**)&Ap, g_Ap);
    cudaGetSymbolAddress((void**)&bnqk, g_bnqk);
    cudaGetSymbolAddress((void**)&bnp, g_bnp);

    cudaFuncSetAttribute(gemm_qk_dual_kernel,
                         cudaFuncAttributeMaxDynamicSharedMemorySize, DSMEM);
    cudaFuncSetAttribute(gemm_proj_kernel,
                         cudaFuncAttributeMaxDynamicSharedMemorySize, PSMEM);

    // prep
    bn_prep_all_kernel<<<3, C_>>>(q_gamma, q_beta, q_mean, q_var,
                                  k_gamma, k_beta, k_mean, k_var,
                                  p_gamma, p_beta, p_mean, p_var, p_b,
                                  bnqk, bnp);
    split_w_all_kernel<<<dim3((C_ * C_ + 255) / 256, 3), 256>>>(q_w, k_w, p_w,
                                                                Aq, Ak, Ap);
    split_x_kernel<<<TBCN / 1024, 256>>>(x, xs);

    // dual q+k GEMM (R12 body, 3-stage), occ 2
    gemm_qk_dual_kernel<<<dim3(2, 8, 128), 192, DSMEM>>>(Aq, Ak, xs, bnqk,
                                                         qlin, klin);

    // fused attn (4-way channel split, 1024 threads/block)
    attn_fuse_kernel<<<B_ * HEADS, 1024>>>(qlin, klin, y);

    // proj GEMM v2 (B reuse across 3 W terms), occ 3
    gemm_proj_kernel<<<dim3(2, 8, 128), 192, PSMEM>>>(Ap, y, bnp, qlin);

    final_lif_kernel<<<BCN / 1024, 256>>>((const float4*)qlin, (float4*)d_out);
}